// round 6
// baseline (speedup 1.0000x reference)
#include <cuda_runtime.h>
#include <math.h>

// Problem shape (fixed): B=2, H=12, S=1024, D=64
#define BB 2
#define HH 12
#define SS 1024
#define DD 64
#define KP 102            // k_precise = int(1024 * 0.1)
#define NROWS (BB*HH*SS)  // 24576

#define TQ 64             // queries per CTA
#define NT 16             // number of key tiles
#define TK 64             // keys per tile
#define THREADS 256
#define QPW 8             // queries per warp (8 warps)

__device__ unsigned long long g_qbits[NROWS];
__device__ unsigned long long g_kbits[NROWS];

// ---------------------------------------------------------------------------
// Kernel 1: pack sign bits. One warp per row.
// ---------------------------------------------------------------------------
__global__ void pack_signs_kernel(const float* __restrict__ q,
                                  const float* __restrict__ k) {
    int warp = (blockIdx.x * blockDim.x + threadIdx.x) >> 5;
    int lane = threadIdx.x & 31;
    if (warp >= 2 * NROWS) return;

    const float* src;
    unsigned long long* dst;
    int row;
    if (warp < NROWS) { src = q; dst = g_qbits; row = warp; }
    else              { src = k; dst = g_kbits; row = warp - NROWS; }

    const float* p = src + (size_t)row * DD;
    unsigned lo = __ballot_sync(0xffffffffu, p[lane]      > 0.0f);
    unsigned hi = __ballot_sync(0xffffffffu, p[lane + 32] > 0.0f);
    if (lane == 0)
        dst[row] = (unsigned long long)lo | ((unsigned long long)hi << 32);
}

// ---------------------------------------------------------------------------
// Kernel 2: one CTA per (bh, 64-query tile). K/V staged through smem tiles.
// ---------------------------------------------------------------------------
// Dynamic smem layout (85,184 bytes):
//   float4 s_q4   [TQ*16]      16384   query rows
//   float4 s_tile [TK*16]      16384   K tile (pass1) / V tile (pass2)
//   u64    s_kb   [SS]          8192   packed key bits
//   float  s_score[TQ*104]     26624   selected scores -> probs
//   int    s_hist [8*66]        2112   per-warp histograms
//   u16    s_sel  [TQ*104]     13312   selected key indices (ascending)
//   u16    s_cnt  [TQ*17]       2176   per-tile rank offsets
#define SMEM_BYTES (16384 + 16384 + 8192 + 26624 + 2112 + 13312 + 2176)

__global__ __launch_bounds__(THREADS, 2)
void attn_kernel(const float* __restrict__ q,
                 const float* __restrict__ k,
                 const float* __restrict__ v,
                 const float* __restrict__ mask,
                 float* __restrict__ out) {
    extern __shared__ char smem[];
    float4* s_q4   = (float4*)smem;
    float4* s_tile = s_q4 + TQ * 16;
    unsigned long long* s_kb = (unsigned long long*)(s_tile + TK * 16);
    float* s_score = (float*)(s_kb + SS);
    int*   s_hist  = (int*)(s_score + TQ * 104);
    unsigned short* s_sel = (unsigned short*)(s_hist + 8 * 66);
    unsigned short* s_cnt = s_sel + TQ * 104;

    const int bh = blockIdx.x >> 4;          // 0..23
    const int q0 = (blockIdx.x & 15) * TQ;   // query tile base within sequence
    const int b  = bh / HH;
    const int tid  = threadIdx.x;
    const int lane = tid & 31;
    const int w    = tid >> 5;
    const unsigned full = 0xffffffffu;
    const unsigned ltm  = (1u << lane) - 1u;

    // ---- stage key bits + q rows ----
    {
        const unsigned long long* kb = g_kbits + (size_t)bh * SS;
        for (int i = tid; i < SS; i += THREADS) s_kb[i] = kb[i];
        const float4* qg = (const float4*)(q + ((size_t)bh * SS + q0) * DD);
        for (int i = tid; i < TQ * 16; i += THREADS) s_q4[i] = qg[i];
    }
    __syncthreads();

    // ================= Pass 0: selection (per warp, 8 queries) =============
    for (int qq = 0; qq < QPW; ++qq) {
        const int qt = w * QPW + qq;
        const unsigned long long qbit = g_qbits[(size_t)bh * SS + q0 + qt];
        int* hist = s_hist + w * 66;
        for (int e = lane; e < 65; e += 32) hist[e] = 0;
        __syncwarp();

        // sweep 1: histogram of popcounts
        #pragma unroll 4
        for (int c = 0; c < 32; ++c) {
            int p = __popcll(qbit ^ s_kb[c * 32 + lane]);
            unsigned grp = __match_any_sync(full, p);
            if ((__ffs(grp) - 1) == lane) atomicAdd(&hist[p], __popc(grp));
        }
        __syncwarp();

        int pstar = 0, r = 0;
        if (lane == 0) {
            int c = 0;
            for (int p = 0; p <= 64; ++p) {
                int nc = c + hist[p];
                if (nc >= KP) { pstar = p; r = KP - c; break; }
                c = nc;
            }
        }
        pstar = __shfl_sync(full, pstar, 0);
        r     = __shfl_sync(full, r, 0);

        // sweep 2: build compacted selected list (ascending index; first-r ties)
        int taken = 0, selcnt = 0;
        unsigned short* sel = s_sel + qt * 104;
        unsigned short* cnt = s_cnt + qt * 17;
        for (int c = 0; c < 32; ++c) {
            if (((c & 1) == 0) && lane == 0) cnt[c >> 1] = (unsigned short)selcnt;
            const int i = c * 32 + lane;
            const int p = __popcll(qbit ^ s_kb[i]);
            const bool lt = (p < pstar);
            const bool eq = (p == pstar);
            const unsigned eqb = __ballot_sync(full, eq);
            const bool sele = eq && (taken + __popc(eqb & ltm) < r);
            const unsigned ball = __ballot_sync(full, lt || sele);
            if (lt || sele) sel[selcnt + __popc(ball & ltm)] = (unsigned short)i;
            selcnt += __popc(ball);
            taken  += __popc(eqb);
        }
        if (lane == 0) cnt[16] = (unsigned short)selcnt;   // == KP
    }
    __syncthreads();

    // ================= Pass 1: precise scores from smem K tiles ============
    const float* kbase = k + (size_t)bh * SS * DD;
    const float* vbase = v + (size_t)bh * SS * DD;
    const float* mrow  = mask + (size_t)b * SS;
    const int l16  = lane & 15;
    const int half = lane >> 4;

    for (int t = 0; t < NT; ++t) {
        const float4* kt = (const float4*)(kbase + (size_t)t * TK * DD);
        for (int i = tid; i < TK * 16; i += THREADS) s_tile[i] = kt[i];
        __syncthreads();

        for (int qq = 0; qq < QPW; ++qq) {
            const int qt = w * QPW + qq;
            const int lo = s_cnt[qt * 17 + t];
            const int cn = s_cnt[qt * 17 + t + 1] - lo;
            const float4 qv = s_q4[qt * 16 + l16];
            const int trips = (cn + 1) >> 1;
            for (int jj = 0; jj < trips; ++jj) {
                const int j = jj * 2 + half;
                const bool valid = (j < cn);
                const int rank = lo + (valid ? j : 0);
                const int key  = s_sel[qt * 104 + rank];
                const float4 kv = s_tile[(key & 63) * 16 + l16];
                float part = qv.x * kv.x + qv.y * kv.y + qv.z * kv.z + qv.w * kv.w;
                part += __shfl_xor_sync(full, part, 8);
                part += __shfl_xor_sync(full, part, 4);
                part += __shfl_xor_sync(full, part, 2);
                part += __shfl_xor_sync(full, part, 1);
                if (l16 == 0 && valid)
                    s_score[qt * 104 + rank] = part * 0.125f + __ldg(&mrow[key]);
            }
        }
        __syncthreads();
    }

    // ================= Softmax (per warp, 8 queries) =======================
    for (int qq = 0; qq < QPW; ++qq) {
        const int qt = w * QPW + qq;
        float* sc = s_score + qt * 104;
        const float a0 = sc[lane];
        const float a1 = sc[lane + 32];
        const float a2 = sc[lane + 64];
        const float a3 = (lane < KP - 96) ? sc[lane + 96] : -INFINITY;
        float mx = fmaxf(fmaxf(a0, a1), fmaxf(a2, a3));
        #pragma unroll
        for (int off = 16; off; off >>= 1)
            mx = fmaxf(mx, __shfl_xor_sync(full, mx, off));
        const float e0 = __expf(a0 - mx);
        const float e1 = __expf(a1 - mx);
        const float e2 = __expf(a2 - mx);
        const float e3 = (lane < KP - 96) ? __expf(a3 - mx) : 0.0f;
        float s = e0 + e1 + e2 + e3;
        #pragma unroll
        for (int off = 16; off; off >>= 1)
            s += __shfl_xor_sync(full, s, off);
        const float inv = 1.0f / s;
        sc[lane]      = e0 * inv;
        sc[lane + 32] = e1 * inv;
        sc[lane + 64] = e2 * inv;
        if (lane < KP - 96) sc[lane + 96] = e3 * inv;
    }

    // ================= Pass 2: prob-weighted V from smem tiles =============
    float accA[QPW], accB[QPW];
    #pragma unroll
    for (int i = 0; i < QPW; ++i) { accA[i] = 0.0f; accB[i] = 0.0f; }

    const float* tileF = (const float*)s_tile;
    for (int t = 0; t < NT; ++t) {
        __syncthreads();   // previous tile fully consumed
        const float4* vt = (const float4*)(vbase + (size_t)t * TK * DD);
        for (int i = tid; i < TK * 16; i += THREADS) s_tile[i] = vt[i];
        __syncthreads();

        #pragma unroll
        for (int qq = 0; qq < QPW; ++qq) {
            const int qt = w * QPW + qq;
            const int lo = s_cnt[qt * 17 + t];
            const int hi = s_cnt[qt * 17 + t + 1];
            for (int j = lo; j < hi; ++j) {
                const int loc = s_sel[qt * 104 + j] & 63;
                const float p = s_score[qt * 104 + j];
                accA[qq] += p * tileF[loc * 64 + lane];
                accB[qq] += p * tileF[loc * 64 + lane + 32];
            }
        }
    }

    // ---- write out (coalesced 128B per half-row) ----
    float* ob = out + ((size_t)bh * SS + q0) * DD;
    #pragma unroll
    for (int qq = 0; qq < QPW; ++qq) {
        const int qt = w * QPW + qq;
        ob[qt * 64 + lane]      = accA[qq];
        ob[qt * 64 + lane + 32] = accB[qq];
    }
}

// ---------------------------------------------------------------------------
extern "C" void kernel_launch(void* const* d_in, const int* in_sizes, int n_in,
                              void* d_out, int out_size) {
    const float* q    = (const float*)d_in[0];
    const float* k    = (const float*)d_in[1];
    const float* v    = (const float*)d_in[2];
    const float* mask = (const float*)d_in[3];
    float* out        = (float*)d_out;

    cudaFuncSetAttribute(attn_kernel,
                         cudaFuncAttributeMaxDynamicSharedMemorySize,
                         SMEM_BYTES);

    {
        int total_threads = 2 * NROWS * 32;
        int block = 256;
        int grid = (total_threads + block - 1) / block;
        pack_signs_kernel<<<grid, block>>>(q, k);
    }
    attn_kernel<<<BB * HH * NT, THREADS, SMEM_BYTES>>>(q, k, v, mask, out);
}

// round 8
// speedup vs baseline: 4.2397x; 4.2397x over previous
#include <cuda_runtime.h>
#include <math.h>

// Problem shape (fixed): B=2, H=12, S=1024, D=64
#define BB 2
#define HH 12
#define SS 1024
#define DD 64
#define KP 102            // k_precise = int(1024 * 0.1)
#define NROWS (BB*HH*SS)  // 24576

__device__ unsigned long long g_kbits[NROWS];

// ---------------------------------------------------------------------------
// Kernel 1: pack key sign bits. One warp per key row.
// ---------------------------------------------------------------------------
__global__ void pack_signs_kernel(const float* __restrict__ k) {
    int warp = (blockIdx.x * blockDim.x + threadIdx.x) >> 5;
    int lane = threadIdx.x & 31;
    if (warp >= NROWS) return;
    const float* p = k + (size_t)warp * DD;
    unsigned lo = __ballot_sync(0xffffffffu, p[lane]      > 0.0f);
    unsigned hi = __ballot_sync(0xffffffffu, p[lane + 32] > 0.0f);
    if (lane == 0)
        g_kbits[warp] = (unsigned long long)lo | ((unsigned long long)hi << 32);
}

// ---------------------------------------------------------------------------
// Kernel 2: one CTA (128 threads = 4 warps) per query.
// ---------------------------------------------------------------------------
__global__ __launch_bounds__(128, 8)
void attn_kernel(const float* __restrict__ q,
                 const float* __restrict__ k,
                 const float* __restrict__ v,
                 const float* __restrict__ mask,
                 float* __restrict__ out) {
    __shared__ float4 s_acc4[8][16];       // v partial sums (16B aligned)
    __shared__ float2 s_pi[KP + 2];        // .x score->prob, .y idx bits
    __shared__ int    s_hist[4 * 66];      // per-warp histograms
    __shared__ int    s_histm[65];         // merged
    __shared__ int    s_wcnt[32];          // packed lt|eq counts per (it,warp)
    __shared__ int    s_idx[KP + 2];       // selected key indices (ascending)
    __shared__ float  s_red[4];
    __shared__ int    s_ps[2];             // pstar, r
    __shared__ unsigned long long s_qbit;

    const int qid  = blockIdx.x;           // 0..B*H*S-1
    const int bh   = qid >> 10;
    const int b    = bh / HH;
    const int tid  = threadIdx.x;
    const int lane = tid & 31;
    const int w    = tid >> 5;
    const unsigned full = 0xffffffffu;
    const unsigned ltm  = (1u << lane) - 1u;

    // ---- query sign bits computed in-block (warp 0) ----
    const float* qrow = q + (size_t)qid * DD;
    if (w == 0) {
        unsigned lo = __ballot_sync(full, qrow[lane]      > 0.0f);
        unsigned hi = __ballot_sync(full, qrow[lane + 32] > 0.0f);
        if (lane == 0)
            s_qbit = (unsigned long long)lo | ((unsigned long long)hi << 32);
    }
    for (int e = lane; e < 65; e += 32) s_hist[w * 66 + e] = 0;
    __syncthreads();
    const unsigned long long qbit = s_qbit;

    // ---- Phase A: popcounts in registers + per-warp histograms ----
    const unsigned long long* kb = g_kbits + (size_t)bh * SS;
    int p_reg[8];
    #pragma unroll
    for (int it = 0; it < 8; ++it) {
        p_reg[it] = __popcll(qbit ^ kb[it * 128 + tid]);
        unsigned grp = __match_any_sync(full, p_reg[it]);
        if ((__ffs(grp) - 1) == lane)
            atomicAdd(&s_hist[w * 66 + p_reg[it]], __popc(grp));
    }
    __syncthreads();
    if (tid < 65)
        s_histm[tid] = s_hist[tid] + s_hist[66 + tid]
                     + s_hist[132 + tid] + s_hist[198 + tid];
    __syncthreads();

    // ---- threshold via warp-0 prefix scan over bins ----
    if (w == 0) {
        int h = s_histm[lane];             // bins 0..31
        int c = h;
        #pragma unroll
        for (int off = 1; off < 32; off <<= 1) {
            int t = __shfl_up_sync(full, c, off);
            if (lane >= off) c += t;
        }
        int tot_lo = __shfl_sync(full, c, 31);
        int pstar, r;
        if (tot_lo >= KP) {
            unsigned bb = __ballot_sync(full, c >= KP);
            int l = __ffs(bb) - 1;
            pstar = l;
            r = KP - __shfl_sync(full, c - h, l);
        } else {
            int h2 = s_histm[32 + lane];   // bins 32..63
            int c2 = h2;
            #pragma unroll
            for (int off = 1; off < 32; off <<= 1) {
                int t = __shfl_up_sync(full, c2, off);
                if (lane >= off) c2 += t;
            }
            c2 += tot_lo;
            unsigned bb = __ballot_sync(full, c2 >= KP);
            if (bb) {
                int l = __ffs(bb) - 1;
                pstar = 32 + l;
                r = KP - __shfl_sync(full, c2 - h2, l);
            } else {
                pstar = 64;
                r = KP - __shfl_sync(full, c2, 31);
            }
        }
        if (lane == 0) { s_ps[0] = pstar; s_ps[1] = r; }
    }
    __syncthreads();
    const int pstar = s_ps[0];
    const int r     = s_ps[1];

    // ---- Phase B: deterministic ordered compaction (no atomics) ----
    #pragma unroll
    for (int it = 0; it < 8; ++it) {
        unsigned lb = __ballot_sync(full, p_reg[it] <  pstar);
        unsigned eb = __ballot_sync(full, p_reg[it] == pstar);
        if (lane == 0)
            s_wcnt[it * 4 + w] = __popc(lb) | (__popc(eb) << 16);
    }
    __syncthreads();
    {
        int vcnt = s_wcnt[lane];
        int c = vcnt;
        #pragma unroll
        for (int off = 1; off < 32; off <<= 1) {
            int t = __shfl_up_sync(full, c, off);
            if (lane >= off) c += t;
        }
        int excl = c - vcnt;
        int nlt  = __shfl_sync(full, c, 31) & 0xffff;   // == KP - r
        #pragma unroll
        for (int it = 0; it < 8; ++it) {
            unsigned lb = __ballot_sync(full, p_reg[it] <  pstar);
            unsigned eb = __ballot_sync(full, p_reg[it] == pstar);
            int pref = __shfl_sync(full, excl, it * 4 + w);
            int i = it * 128 + tid;
            if (p_reg[it] < pstar) {
                s_idx[(pref & 0xffff) + __popc(lb & ltm)] = i;
            } else if (p_reg[it] == pstar) {
                int rk = (pref >> 16) + __popc(eb & ltm);
                if (rk < r) s_idx[nlt + rk] = i;
            }
        }
    }
    __syncthreads();

    // ---- Phase C1: precise scores, 8-lane groups, 4 keys/warp-iter ----
    const float* kbase = k + (size_t)bh * SS * DD;
    const float* mrow  = mask + (size_t)b * SS;
    {
        const int grp4 = lane >> 3;
        const int l8   = lane & 7;
        const float4* qr4 = (const float4*)qrow;
        const float4 qv0 = qr4[l8];
        const float4 qv1 = qr4[l8 + 8];
        #pragma unroll
        for (int i = 0; i < 7; ++i) {
            const int j = i * 16 + w * 4 + grp4;
            const bool valid = (j < KP);
            const int idx = s_idx[valid ? j : 0];
            const float4* kr = (const float4*)(kbase + (size_t)idx * DD);
            const float4 k0 = kr[l8];
            const float4 k1 = kr[l8 + 8];
            float part = qv0.x * k0.x + qv0.y * k0.y + qv0.z * k0.z + qv0.w * k0.w
                       + qv1.x * k1.x + qv1.y * k1.y + qv1.z * k1.z + qv1.w * k1.w;
            part += __shfl_xor_sync(full, part, 4);
            part += __shfl_xor_sync(full, part, 2);
            part += __shfl_xor_sync(full, part, 1);
            if (valid && l8 == 0)
                s_pi[j].x = part * 0.125f + __ldg(&mrow[idx]);
        }
    }
    __syncthreads();

    // ---- softmax (normalized probs written packed with idx) ----
    {
        const float sc = (tid < KP) ? s_pi[tid].x : -INFINITY;
        float mx = sc;
        #pragma unroll
        for (int off = 16; off; off >>= 1)
            mx = fmaxf(mx, __shfl_xor_sync(full, mx, off));
        if (lane == 0) s_red[w] = mx;
        __syncthreads();
        const float m = fmaxf(fmaxf(s_red[0], s_red[1]),
                              fmaxf(s_red[2], s_red[3]));
        __syncthreads();
        const float e = (tid < KP) ? __expf(sc - m) : 0.0f;
        float sm = e;
        #pragma unroll
        for (int off = 16; off; off >>= 1)
            sm += __shfl_xor_sync(full, sm, off);
        if (lane == 0) s_red[w] = sm;
        __syncthreads();
        const float inv = 1.0f / (s_red[0] + s_red[1] + s_red[2] + s_red[3]);
        if (tid < KP)
            s_pi[tid] = make_float2(e * inv, __int_as_float(s_idx[tid]));
    }
    __syncthreads();

    // ---- Phase C2: prob-weighted V; 16-lane groups, 1 LDG.128 per key ----
    const float* vbase = v + (size_t)bh * SS * DD;
    {
        const int g   = tid >> 4;          // 0..7
        const int l16 = tid & 15;
        const int lo  = g * 13;
        const int hi  = (lo + 13 < KP) ? lo + 13 : KP;
        float4 acc = make_float4(0.f, 0.f, 0.f, 0.f);
        for (int j = lo; j < hi; ++j) {
            const float2 pi = s_pi[j];
            const int idx = __float_as_int(pi.y);
            const float4 vv =
                ((const float4*)(vbase + (size_t)idx * DD))[l16];
            acc.x += pi.x * vv.x;
            acc.y += pi.x * vv.y;
            acc.z += pi.x * vv.z;
            acc.w += pi.x * vv.w;
        }
        s_acc4[g][l16] = acc;
    }
    __syncthreads();
    if (tid < DD) {
        const float* col = (const float*)&s_acc4[0][0] + tid;
        float s = 0.0f;
        #pragma unroll
        for (int g = 0; g < 8; ++g) s += col[g * DD];
        out[(size_t)qid * DD + tid] = s;
    }
}

// ---------------------------------------------------------------------------
extern "C" void kernel_launch(void* const* d_in, const int* in_sizes, int n_in,
                              void* d_out, int out_size) {
    const float* q    = (const float*)d_in[0];
    const float* k    = (const float*)d_in[1];
    const float* v    = (const float*)d_in[2];
    const float* mask = (const float*)d_in[3];
    float* out        = (float*)d_out;

    {
        int total_threads = NROWS * 32;
        int block = 256;
        int grid = (total_threads + block - 1) / block;
        pack_signs_kernel<<<grid, block>>>(k);
    }
    attn_kernel<<<NROWS, 128>>>(q, k, v, mask, out);
}

// round 13
// speedup vs baseline: 4.9707x; 1.1724x over previous
#include <cuda_runtime.h>
#include <math.h>

// Problem shape (fixed): B=2, H=12, S=1024, D=64
#define BB 2
#define HH 12
#define SS 1024
#define DD 64
#define KP 102            // k_precise = int(1024 * 0.1)
#define NROWS (BB*HH*SS)  // 24576

__device__ unsigned long long g_kbits[NROWS];

// ---------------------------------------------------------------------------
// Kernel 1: pack key sign bits. One warp per key row.
// ---------------------------------------------------------------------------
__global__ void pack_signs_kernel(const float* __restrict__ k) {
    int warp = (blockIdx.x * blockDim.x + threadIdx.x) >> 5;
    int lane = threadIdx.x & 31;
    if (warp >= NROWS) return;
    const float* p = k + (size_t)warp * DD;
    unsigned lo = __ballot_sync(0xffffffffu, p[lane]      > 0.0f);
    unsigned hi = __ballot_sync(0xffffffffu, p[lane + 32] > 0.0f);
    if (lane == 0)
        g_kbits[warp] = (unsigned long long)lo | ((unsigned long long)hi << 32);
}

// ---------------------------------------------------------------------------
// Kernel 2: one CTA (128 threads = 4 warps) per query.
// ---------------------------------------------------------------------------
__global__ __launch_bounds__(128, 12)
void attn_kernel(const float* __restrict__ q,
                 const float* __restrict__ k,
                 const float* __restrict__ v,
                 const float* __restrict__ mask,
                 float* __restrict__ out) {
    __shared__ float4 s_acc4[8][16];        // v partial sums (16B aligned)
    __shared__ float2 s_pi[KP + 2];         // .x prob, .y idx bits
    __shared__ unsigned char s_popc[SS];    // popcounts (reg-pressure relief)
    __shared__ int    s_hist[4 * 66];       // per-warp histograms
    __shared__ int    s_histm[65];          // merged
    __shared__ int    s_wcnt[32];           // packed lt|eq counts per (it,warp)
    __shared__ int    s_idx[KP + 2];        // selected key indices (ascending)
    __shared__ float  s_red[4];
    __shared__ int    s_ps[2];              // pstar, r
    __shared__ unsigned long long s_qbit;

    const int qid  = blockIdx.x;            // 0..B*H*S-1
    const int bh   = qid >> 10;
    const int b    = bh / HH;
    const int tid  = threadIdx.x;
    const int lane = tid & 31;
    const int w    = tid >> 5;
    const unsigned full = 0xffffffffu;
    const unsigned ltm  = (1u << lane) - 1u;

    // ---- query sign bits computed in-block (warp 0) ----
    const float* qrow = q + (size_t)qid * DD;
    if (w == 0) {
        unsigned lo = __ballot_sync(full, qrow[lane]      > 0.0f);
        unsigned hi = __ballot_sync(full, qrow[lane + 32] > 0.0f);
        if (lane == 0)
            s_qbit = (unsigned long long)lo | ((unsigned long long)hi << 32);
    }
    for (int e = lane; e < 65; e += 32) s_hist[w * 66 + e] = 0;
    __syncthreads();
    const unsigned long long qbit = s_qbit;

    // ---- Phase A: popcounts -> shared + per-warp histograms ----
    const unsigned long long* kb = g_kbits + (size_t)bh * SS;
    #pragma unroll
    for (int it = 0; it < 8; ++it) {
        const int p = __popcll(qbit ^ kb[it * 128 + tid]);
        s_popc[it * 128 + tid] = (unsigned char)p;
        unsigned grp = __match_any_sync(full, p);
        if ((__ffs(grp) - 1) == lane)
            atomicAdd(&s_hist[w * 66 + p], __popc(grp));
    }
    __syncthreads();
    if (tid < 65)
        s_histm[tid] = s_hist[tid] + s_hist[66 + tid]
                     + s_hist[132 + tid] + s_hist[198 + tid];
    __syncthreads();

    // ---- threshold via warp-0 prefix scan over bins ----
    if (w == 0) {
        int h = s_histm[lane];              // bins 0..31
        int c = h;
        #pragma unroll
        for (int off = 1; off < 32; off <<= 1) {
            int t = __shfl_up_sync(full, c, off);
            if (lane >= off) c += t;
        }
        int tot_lo = __shfl_sync(full, c, 31);
        int pstar, r;
        if (tot_lo >= KP) {
            unsigned bb = __ballot_sync(full, c >= KP);
            int l = __ffs(bb) - 1;
            pstar = l;
            r = KP - __shfl_sync(full, c - h, l);
        } else {
            int h2 = s_histm[32 + lane];    // bins 32..63
            int c2 = h2;
            #pragma unroll
            for (int off = 1; off < 32; off <<= 1) {
                int t = __shfl_up_sync(full, c2, off);
                if (lane >= off) c2 += t;
            }
            c2 += tot_lo;
            unsigned bb = __ballot_sync(full, c2 >= KP);
            if (bb) {
                int l = __ffs(bb) - 1;
                pstar = 32 + l;
                r = KP - __shfl_sync(full, c2 - h2, l);
            } else {
                pstar = 64;
                r = KP - __shfl_sync(full, c2, 31);
            }
        }
        if (lane == 0) { s_ps[0] = pstar; s_ps[1] = r; }
    }
    __syncthreads();
    const int pstar = s_ps[0];
    const int r     = s_ps[1];

    // ---- Phase B: deterministic ordered compaction (no atomics) ----
    #pragma unroll
    for (int it = 0; it < 8; ++it) {
        const int p = s_popc[it * 128 + tid];
        unsigned lb = __ballot_sync(full, p <  pstar);
        unsigned eb = __ballot_sync(full, p == pstar);
        if (lane == 0)
            s_wcnt[it * 4 + w] = __popc(lb) | (__popc(eb) << 16);
    }
    __syncthreads();
    {
        int vcnt = s_wcnt[lane];
        int c = vcnt;
        #pragma unroll
        for (int off = 1; off < 32; off <<= 1) {
            int t = __shfl_up_sync(full, c, off);
            if (lane >= off) c += t;
        }
        int excl = c - vcnt;
        int nlt  = __shfl_sync(full, c, 31) & 0xffff;   // == KP - r
        #pragma unroll
        for (int it = 0; it < 8; ++it) {
            const int p = s_popc[it * 128 + tid];
            unsigned lb = __ballot_sync(full, p <  pstar);
            unsigned eb = __ballot_sync(full, p == pstar);
            int pref = __shfl_sync(full, excl, it * 4 + w);
            int i = it * 128 + tid;
            if (p < pstar) {
                s_idx[(pref & 0xffff) + __popc(lb & ltm)] = i;
            } else if (p == pstar) {
                int rk = (pref >> 16) + __popc(eb & ltm);
                if (rk < r) s_idx[nlt + rk] = i;
            }
        }
    }
    __syncthreads();

    // ---- Phase C1: precise scores, 8-lane groups, 4 keys/warp-iter ----
    const float* kbase = k + (size_t)bh * SS * DD;
    const float* mrow  = mask + (size_t)b * SS;
    {
        const int grp4 = lane >> 3;
        const int l8   = lane & 7;
        const float4* qr4 = (const float4*)qrow;
        const float4 qv0 = qr4[l8];
        const float4 qv1 = qr4[l8 + 8];
        #pragma unroll 2
        for (int i = 0; i < 7; ++i) {
            const int j = i * 16 + w * 4 + grp4;
            const bool valid = (j < KP);
            const int idx = s_idx[valid ? j : 0];
            const float4* kr = (const float4*)(kbase + (size_t)idx * DD);
            const float4 k0 = kr[l8];
            const float4 k1 = kr[l8 + 8];
            float part = qv0.x * k0.x + qv0.y * k0.y + qv0.z * k0.z + qv0.w * k0.w
                       + qv1.x * k1.x + qv1.y * k1.y + qv1.z * k1.z + qv1.w * k1.w;
            part += __shfl_xor_sync(full, part, 4);
            part += __shfl_xor_sync(full, part, 2);
            part += __shfl_xor_sync(full, part, 1);
            if (valid && l8 == 0)
                s_pi[j].x = part * 0.125f + __ldg(&mrow[idx]);
        }
    }
    __syncthreads();

    // ---- softmax (normalized probs written packed with idx) ----
    {
        const float sc = (tid < KP) ? s_pi[tid].x : -INFINITY;
        float mx = sc;
        #pragma unroll
        for (int off = 16; off; off >>= 1)
            mx = fmaxf(mx, __shfl_xor_sync(full, mx, off));
        if (lane == 0) s_red[w] = mx;
        __syncthreads();
        const float m = fmaxf(fmaxf(s_red[0], s_red[1]),
                              fmaxf(s_red[2], s_red[3]));
        __syncthreads();
        const float e = (tid < KP) ? __expf(sc - m) : 0.0f;
        float sm = e;
        #pragma unroll
        for (int off = 16; off; off >>= 1)
            sm += __shfl_xor_sync(full, sm, off);
        if (lane == 0) s_red[w] = sm;
        __syncthreads();
        const float inv = 1.0f / (s_red[0] + s_red[1] + s_red[2] + s_red[3]);
        if (tid < KP)
            s_pi[tid] = make_float2(e * inv, __int_as_float(s_idx[tid]));
    }
    __syncthreads();

    // ---- Phase C2: prob-weighted V; 16-lane groups, 1 LDG.128 per key ----
    const float* vbase = v + (size_t)bh * SS * DD;
    {
        const int g   = tid >> 4;           // 0..7
        const int l16 = tid & 15;
        const int lo  = g * 13;
        const int hi  = (lo + 13 < KP) ? lo + 13 : KP;
        float4 acc = make_float4(0.f, 0.f, 0.f, 0.f);
        #pragma unroll 2
        for (int j = lo; j < hi; ++j) {
            const float2 pi = s_pi[j];
            const int idx = __float_as_int(pi.y);
            const float4 vv =
                ((const float4*)(vbase + (size_t)idx * DD))[l16];
            acc.x += pi.x * vv.x;
            acc.y += pi.x * vv.y;
            acc.z += pi.x * vv.z;
            acc.w += pi.x * vv.w;
        }
        s_acc4[g][l16] = acc;
    }
    __syncthreads();
    if (tid < DD) {
        const float* col = (const float*)&s_acc4[0][0] + tid;
        float s = 0.0f;
        #pragma unroll
        for (int g = 0; g < 8; ++g) s += col[g * DD];
        out[(size_t)qid * DD + tid] = s;
    }
}

// ---------------------------------------------------------------------------
extern "C" void kernel_launch(void* const* d_in, const int* in_sizes, int n_in,
                              void* d_out, int out_size) {
    const float* q    = (const float*)d_in[0];
    const float* k    = (const float*)d_in[1];
    const float* v    = (const float*)d_in[2];
    const float* mask = (const float*)d_in[3];
    float* out        = (float*)d_out;

    {
        int total_threads = NROWS * 32;
        int block = 256;
        int grid = (total_threads + block - 1) / block;
        pack_signs_kernel<<<grid, block>>>(k);
    }
    attn_kernel<<<NROWS, 128>>>(q, k, v, mask, out);
}

// round 14
// speedup vs baseline: 5.0365x; 1.0132x over previous
#include <cuda_runtime.h>
#include <cuda_fp16.h>
#include <math.h>

// Problem shape (fixed): B=2, H=12, S=1024, D=64
#define BB 2
#define HH 12
#define SS 1024
#define DD 64
#define KP 102            // k_precise = int(1024 * 0.1)
#define NROWS (BB*HH*SS)  // 24576

__device__ unsigned long long g_kbits[NROWS];
__device__ __half2 g_kh[NROWS * DD / 2];   // fp16 copy of K (3.1 MB)
__device__ __half2 g_vh[NROWS * DD / 2];   // fp16 copy of V (3.1 MB)

// ---------------------------------------------------------------------------
// Kernel 1: pack key sign bits. One warp per key row. (fp32 signs — selection
// stays bit-identical to the reference.)
// ---------------------------------------------------------------------------
__global__ void pack_signs_kernel(const float* __restrict__ k) {
    int warp = (blockIdx.x * blockDim.x + threadIdx.x) >> 5;
    int lane = threadIdx.x & 31;
    if (warp >= NROWS) return;
    const float* p = k + (size_t)warp * DD;
    unsigned lo = __ballot_sync(0xffffffffu, p[lane]      > 0.0f);
    unsigned hi = __ballot_sync(0xffffffffu, p[lane + 32] > 0.0f);
    if (lane == 0)
        g_kbits[warp] = (unsigned long long)lo | ((unsigned long long)hi << 32);
}

// ---------------------------------------------------------------------------
// Kernel 1b: fp32 -> fp16 copies of K and V. One float4 per thread per tensor.
// ---------------------------------------------------------------------------
__global__ void convert_half_kernel(const float* __restrict__ k,
                                    const float* __restrict__ v) {
    int i = blockIdx.x * blockDim.x + threadIdx.x;
    if (i >= NROWS * DD / 4) return;
    float4 kv = ((const float4*)k)[i];
    g_kh[i * 2]     = __float22half2_rn(make_float2(kv.x, kv.y));
    g_kh[i * 2 + 1] = __float22half2_rn(make_float2(kv.z, kv.w));
    float4 vv = ((const float4*)v)[i];
    g_vh[i * 2]     = __float22half2_rn(make_float2(vv.x, vv.y));
    g_vh[i * 2 + 1] = __float22half2_rn(make_float2(vv.z, vv.w));
}

// ---------------------------------------------------------------------------
// Kernel 2: one CTA (128 threads = 4 warps) per query.
// ---------------------------------------------------------------------------
__global__ __launch_bounds__(128, 12)
void attn_kernel(const float* __restrict__ q,
                 const float* __restrict__ mask,
                 float* __restrict__ out) {
    __shared__ float4 s_acc4[8][16];        // v partial sums (16B aligned)
    __shared__ float2 s_pi[KP + 2];         // .x prob, .y idx bits
    __shared__ int    s_hist[4 * 66];       // per-warp histograms
    __shared__ int    s_histm[65];          // merged
    __shared__ int    s_wcnt[32];           // packed lt|eq counts per (it,warp)
    __shared__ unsigned s_lb[32];           // lt ballots per (it,warp)
    __shared__ unsigned s_eb[32];           // eq ballots per (it,warp)
    __shared__ unsigned char s_popc[SS];    // popcounts
    __shared__ int    s_idx[KP + 2];        // selected key indices (ascending)
    __shared__ float  s_red[4];
    __shared__ int    s_ps[2];              // pstar, r
    __shared__ unsigned long long s_qbit;

    const int qid  = blockIdx.x;            // 0..B*H*S-1
    const int bh   = qid >> 10;
    const int b    = bh / HH;
    const int tid  = threadIdx.x;
    const int lane = tid & 31;
    const int w    = tid >> 5;
    const unsigned full = 0xffffffffu;
    const unsigned ltm  = (1u << lane) - 1u;

    // ---- query sign bits computed in-block (warp 0) ----
    const float* qrow = q + (size_t)qid * DD;
    if (w == 0) {
        unsigned lo = __ballot_sync(full, qrow[lane]      > 0.0f);
        unsigned hi = __ballot_sync(full, qrow[lane + 32] > 0.0f);
        if (lane == 0)
            s_qbit = (unsigned long long)lo | ((unsigned long long)hi << 32);
    }
    for (int e = lane; e < 65; e += 32) s_hist[w * 66 + e] = 0;
    __syncthreads();
    const unsigned long long qbit = s_qbit;

    // ---- Phase A: popcounts -> shared + per-warp histograms ----
    const unsigned long long* kb = g_kbits + (size_t)bh * SS;
    #pragma unroll
    for (int it = 0; it < 8; ++it) {
        const int p = __popcll(qbit ^ kb[it * 128 + tid]);
        s_popc[it * 128 + tid] = (unsigned char)p;
        unsigned grp = __match_any_sync(full, p);
        if ((__ffs(grp) - 1) == lane)
            atomicAdd(&s_hist[w * 66 + p], __popc(grp));
    }
    __syncthreads();
    if (tid < 65)
        s_histm[tid] = s_hist[tid] + s_hist[66 + tid]
                     + s_hist[132 + tid] + s_hist[198 + tid];
    __syncthreads();

    // ---- threshold via warp-0 prefix scan over bins ----
    if (w == 0) {
        int h = s_histm[lane];              // bins 0..31
        int c = h;
        #pragma unroll
        for (int off = 1; off < 32; off <<= 1) {
            int t = __shfl_up_sync(full, c, off);
            if (lane >= off) c += t;
        }
        int tot_lo = __shfl_sync(full, c, 31);
        int pstar, r;
        if (tot_lo >= KP) {
            unsigned bb = __ballot_sync(full, c >= KP);
            int l = __ffs(bb) - 1;
            pstar = l;
            r = KP - __shfl_sync(full, c - h, l);
        } else {
            int h2 = s_histm[32 + lane];    // bins 32..63
            int c2 = h2;
            #pragma unroll
            for (int off = 1; off < 32; off <<= 1) {
                int t = __shfl_up_sync(full, c2, off);
                if (lane >= off) c2 += t;
            }
            c2 += tot_lo;
            unsigned bb = __ballot_sync(full, c2 >= KP);
            if (bb) {
                int l = __ffs(bb) - 1;
                pstar = 32 + l;
                r = KP - __shfl_sync(full, c2 - h2, l);
            } else {
                pstar = 64;
                r = KP - __shfl_sync(full, c2, 31);
            }
        }
        if (lane == 0) { s_ps[0] = pstar; s_ps[1] = r; }
    }
    __syncthreads();
    const int pstar = s_ps[0];
    const int r     = s_ps[1];

    // ---- Phase B: deterministic ordered compaction (no atomics) ----
    #pragma unroll
    for (int it = 0; it < 8; ++it) {
        const int p = s_popc[it * 128 + tid];
        unsigned lb = __ballot_sync(full, p <  pstar);
        unsigned eb = __ballot_sync(full, p == pstar);
        if (lane == 0) {
            s_wcnt[it * 4 + w] = __popc(lb) | (__popc(eb) << 16);
            s_lb[it * 4 + w] = lb;
            s_eb[it * 4 + w] = eb;
        }
    }
    __syncthreads();
    {
        int vcnt = s_wcnt[lane];
        int c = vcnt;
        #pragma unroll
        for (int off = 1; off < 32; off <<= 1) {
            int t = __shfl_up_sync(full, c, off);
            if (lane >= off) c += t;
        }
        int excl = c - vcnt;
        int nlt  = __shfl_sync(full, c, 31) & 0xffff;   // == KP - r
        #pragma unroll
        for (int it = 0; it < 8; ++it) {
            const unsigned lb = s_lb[it * 4 + w];
            const unsigned eb = s_eb[it * 4 + w];
            int pref = __shfl_sync(full, excl, it * 4 + w);
            int i = it * 128 + tid;
            if ((lb >> lane) & 1u) {
                s_idx[(pref & 0xffff) + __popc(lb & ltm)] = i;
            } else if ((eb >> lane) & 1u) {
                int rk = (pref >> 16) + __popc(eb & ltm);
                if (rk < r) s_idx[nlt + rk] = i;
            }
        }
    }
    __syncthreads();

    // ---- Phase C1: precise scores from fp16 K; 1 LDG.128 per key ----
    const __half2* kbase = g_kh + (size_t)bh * SS * 32;
    const float* mrow    = mask + (size_t)b * SS;
    {
        const int grp4 = lane >> 3;
        const int l8   = lane & 7;
        const float4* qr4 = (const float4*)qrow;
        const float4 qa = qr4[l8 * 2];       // dims l8*8 .. l8*8+3
        const float4 qb = qr4[l8 * 2 + 1];   // dims l8*8+4 .. l8*8+7
        #pragma unroll 2
        for (int i = 0; i < 7; ++i) {
            const int j = i * 16 + w * 4 + grp4;
            const bool valid = (j < KP);
            const int idx = s_idx[valid ? j : 0];
            const uint4 raw =
                *(const uint4*)(kbase + (size_t)idx * 32 + l8 * 4);
            const float2 f0 = __half22float2(*(const __half2*)&raw.x);
            const float2 f1 = __half22float2(*(const __half2*)&raw.y);
            const float2 f2 = __half22float2(*(const __half2*)&raw.z);
            const float2 f3 = __half22float2(*(const __half2*)&raw.w);
            float part = qa.x * f0.x + qa.y * f0.y + qa.z * f1.x + qa.w * f1.y
                       + qb.x * f2.x + qb.y * f2.y + qb.z * f3.x + qb.w * f3.y;
            part += __shfl_xor_sync(full, part, 4);
            part += __shfl_xor_sync(full, part, 2);
            part += __shfl_xor_sync(full, part, 1);
            if (valid && l8 == 0)
                s_pi[j].x = part * 0.125f + __ldg(&mrow[idx]);
        }
    }
    __syncthreads();

    // ---- softmax (normalized probs written packed with idx) ----
    {
        const float sc = (tid < KP) ? s_pi[tid].x : -INFINITY;
        float mx = sc;
        #pragma unroll
        for (int off = 16; off; off >>= 1)
            mx = fmaxf(mx, __shfl_xor_sync(full, mx, off));
        if (lane == 0) s_red[w] = mx;
        __syncthreads();
        const float m = fmaxf(fmaxf(s_red[0], s_red[1]),
                              fmaxf(s_red[2], s_red[3]));
        __syncthreads();
        const float e = (tid < KP) ? __expf(sc - m) : 0.0f;
        float sm = e;
        #pragma unroll
        for (int off = 16; off; off >>= 1)
            sm += __shfl_xor_sync(full, sm, off);
        if (lane == 0) s_red[w] = sm;
        __syncthreads();
        const float inv = 1.0f / (s_red[0] + s_red[1] + s_red[2] + s_red[3]);
        if (tid < KP)
            s_pi[tid] = make_float2(e * inv, __int_as_float(s_idx[tid]));
    }
    __syncthreads();

    // ---- Phase C2: prob-weighted V from fp16 V; 1 line per key ----
    const __half2* vbase = g_vh + (size_t)bh * SS * 32;
    {
        const int g   = tid >> 4;           // 0..7
        const int l16 = tid & 15;
        const int lo  = g * 13;
        const int hi  = (lo + 13 < KP) ? lo + 13 : KP;
        float4 acc = make_float4(0.f, 0.f, 0.f, 0.f);
        #pragma unroll 2
        for (int j = lo; j < hi; ++j) {
            const float2 pi = s_pi[j];
            const int idx = __float_as_int(pi.y);
            const uint2 raw =
                *(const uint2*)(vbase + (size_t)idx * 32 + l16 * 2);
            const float2 v0 = __half22float2(*(const __half2*)&raw.x);
            const float2 v1 = __half22float2(*(const __half2*)&raw.y);
            acc.x += pi.x * v0.x;
            acc.y += pi.x * v0.y;
            acc.z += pi.x * v1.x;
            acc.w += pi.x * v1.y;
        }
        s_acc4[g][l16] = acc;
    }
    __syncthreads();
    if (tid < DD) {
        const float* col = (const float*)&s_acc4[0][0] + tid;
        float s = 0.0f;
        #pragma unroll
        for (int g = 0; g < 8; ++g) s += col[g * DD];
        out[(size_t)qid * DD + tid] = s;
    }
}

// ---------------------------------------------------------------------------
extern "C" void kernel_launch(void* const* d_in, const int* in_sizes, int n_in,
                              void* d_out, int out_size) {
    const float* q    = (const float*)d_in[0];
    const float* k    = (const float*)d_in[1];
    const float* v    = (const float*)d_in[2];
    const float* mask = (const float*)d_in[3];
    float* out        = (float*)d_out;

    {
        int total_threads = NROWS * 32;
        int block = 256;
        int grid = (total_threads + block - 1) / block;
        pack_signs_kernel<<<grid, block>>>(k);
    }
    {
        int n = NROWS * DD / 4;
        convert_half_kernel<<<(n + 255) / 256, 256>>>(k, v);
    }
    attn_kernel<<<NROWS, 128>>>(q, mask, out);
}